// round 9
// baseline (speedup 1.0000x reference)
#include <cuda_runtime.h>
#include <cuda_bf16.h>
#include <math.h>

#define TT   2048
#define HH   16
#define DQK  192
#define NOPE 128
#define ROPE 64
#define LORA 512
#define VD   128
#define SCALE_F (0.07216878364870322f)  // 1/sqrt(192)

typedef unsigned long long ull;

// Packed dual-fp32 ops (sm_100+). Per-component fma.rn => numerics identical to scalar fp32.
#define FMA2(acc, a, b) asm("fma.rn.f32x2 %0, %1, %2, %0;" : "+l"(acc) : "l"(a), "l"(b))
#define MUL2(acc, b)    asm("mul.rn.f32x2 %0, %0, %1;"     : "+l"(acc) : "l"(b))
#define PACK2(d, lo, hi) asm("mov.b64 %0, {%1, %2};" : "=l"(d) : "f"(lo), "f"(hi))
#define UNPACK2(lo, hi, s) asm("mov.b64 {%0, %1}, %2;" : "=f"(lo), "=f"(hi) : "l"(s))

// Scratch (allowed: __device__ globals, no runtime allocation)
__device__ float g_K[HH * TT * DQK];   // per-head K = [k_nope | k_pe]
__device__ float g_V[HH * TT * VD];    // per-head effective V = k_c @ w_uv[h]

// ---------------------------------------------------------------------------
// Projection kernel (unchanged — isolate the attention change this round)
// ---------------------------------------------------------------------------
__global__ __launch_bounds__(256)
void proj_kernel(const float* __restrict__ kc, const float* __restrict__ wkv,
                 const float* __restrict__ wuv, const float* __restrict__ kpe)
{
    const int rbase = blockIdx.x * 64;
    const int h     = blockIdx.y;
    const int which = blockIdx.z;

    __shared__ float a_s[32 * 68];
    __shared__ float b_s[32 * 132];

    const int tid = threadIdx.x;
    const int ty  = tid >> 4;
    const int tx  = tid & 15;

    float acc[4][8];
    #pragma unroll
    for (int i = 0; i < 4; i++)
        #pragma unroll
        for (int j = 0; j < 8; j++) acc[i][j] = 0.0f;

    const float* Bp      = (which == 0) ? (wkv + h * 256) : (wuv + (size_t)h * LORA * VD);
    const int    bstride = (which == 0) ? (HH * 256) : VD;

    for (int lc = 0; lc < LORA; lc += 32) {
        #pragma unroll
        for (int i = tid; i < 64 * 32; i += 256) {
            int row = i >> 5, l = i & 31;
            a_s[l * 68 + row] = kc[(rbase + row) * LORA + lc + l];
        }
        #pragma unroll
        for (int i = tid; i < 32 * 128; i += 256) {
            int l = i >> 7, n = i & 127;
            b_s[l * 132 + n] = Bp[(size_t)(lc + l) * bstride + n];
        }
        __syncthreads();

        #pragma unroll
        for (int kk = 0; kk < 32; kk++) {
            float4 a4 = *(const float4*)&a_s[kk * 68 + ty * 4];
            float4 b0 = *(const float4*)&b_s[kk * 132 + tx * 8];
            float4 b1 = *(const float4*)&b_s[kk * 132 + tx * 8 + 4];
            float av[4] = {a4.x, a4.y, a4.z, a4.w};
            float bv[8] = {b0.x, b0.y, b0.z, b0.w, b1.x, b1.y, b1.z, b1.w};
            #pragma unroll
            for (int ii = 0; ii < 4; ii++)
                #pragma unroll
                for (int jj = 0; jj < 8; jj++)
                    acc[ii][jj] += av[ii] * bv[jj];
        }
        __syncthreads();
    }

    if (which == 0) {
        #pragma unroll
        for (int ii = 0; ii < 4; ii++) {
            int t = rbase + ty * 4 + ii;
            float* dst = &g_K[((size_t)h * TT + t) * DQK + tx * 8];
            #pragma unroll
            for (int jj = 0; jj < 8; jj++) dst[jj] = acc[ii][jj];
        }
        #pragma unroll
        for (int i = tid; i < 64 * 64; i += 256) {
            int row = i >> 6, dd = i & 63;
            g_K[((size_t)h * TT + rbase + row) * DQK + NOPE + dd] =
                kpe[(rbase + row) * ROPE + dd];
        }
    } else {
        #pragma unroll
        for (int ii = 0; ii < 4; ii++) {
            int t = rbase + ty * 4 + ii;
            float* dst = &g_V[((size_t)h * TT + t) * VD + tx * 8];
            #pragma unroll
            for (int jj = 0; jj < 8; jj++) dst[jj] = acc[ii][jj];
        }
    }
}

// ---------------------------------------------------------------------------
// Causal flash attention v3: packed f32x2 FMAs throughout.
// 128-query x 64-key tiles, 256 threads, 1 CTA/SM.
// smem (floats):
//   q_t  [192][128]        transposed Q (row-pairs load as packed f32x2)
//   k_dup[64][130]         current 64-dim K chunk, each value DUPLICATED (k,k)
//   v_s  [64][128]         V tile
//   P2   [128][130]        scores (even slots) then duplicated probs (p,p)
//   m/l/sc [128]           softmax state
// Total = 58112 floats = 232448 B = 227 KB (the opt-in cap).
// ---------------------------------------------------------------------------
#define QT_OFF   0
#define KD_OFF   (192 * 128)                 // 24576
#define VS_OFF   (KD_OFF + 64 * 130)         // 32896
#define P2_OFF   (VS_OFF + 64 * 128)         // 41088
#define MS_OFF   (P2_OFF + 128 * 130)        // 57728
#define ATTN_SMEM_FLOATS (MS_OFF + 3 * 128)  // 58112

__global__ __launch_bounds__(256, 1)
void attn_kernel(const float* __restrict__ q, float* __restrict__ out)
{
    extern __shared__ float sm[];
    float* q_t   = sm + QT_OFF;
    float* k_dup = sm + KD_OFF;
    float* v_s   = sm + VS_OFF;
    float* P2    = sm + P2_OFF;
    float* m_s   = sm + MS_OFF;
    float* l_s   = m_s + 128;
    float* sc_s  = l_s + 128;

    const int h     = blockIdx.y;
    const int qt    = (int)gridDim.x - 1 - (int)blockIdx.x;  // big tiles first
    const int qbase = qt * 128;
    const int tid   = threadIdx.x;
    const int ty    = tid >> 4;              // 0..15 -> rows ty*8 .. ty*8+7
    const int tx    = tid & 15;              // phase A cols {tx+16m}, phase C cols {4tx,64+4tx}

    // --- Stage Q transposed: q_t[d][r] (conflict-free STS: banks = r%32) ---
    {
        const int r    = tid & 127;
        const int half = tid >> 7;           // 0..1 -> dims half*96 .. +95
        const float* src = &q[((size_t)(qbase + r) * HH + h) * DQK + half * 96];
        #pragma unroll
        for (int g = 0; g < 24; g++) {
            float4 v4 = *(const float4*)(src + g * 4);
            int d = half * 96 + g * 4;
            q_t[(d + 0) * 128 + r] = v4.x;
            q_t[(d + 1) * 128 + r] = v4.y;
            q_t[(d + 2) * 128 + r] = v4.z;
            q_t[(d + 3) * 128 + r] = v4.w;
        }
    }
    if (tid < 128) { m_s[tid] = -3.0e38f; l_s[tid] = 0.0f; }

    ull o2[8][4];
    #pragma unroll
    for (int i = 0; i < 8; i++)
        #pragma unroll
        for (int p = 0; p < 4; p++) o2[i][p] = 0ULL;

    __syncthreads();

    const float* Kg = g_K + (size_t)h * TT * DQK;
    const float* Vg = g_V + (size_t)h * TT * VD;
    const int ntiles = 2 * qt + 2;

    for (int tile = 0; tile < ntiles; tile++) {
        const int sbase = tile * 64;

        // --- Phase A: S = Q K^T over 3 chunks of 64 dims (packed) ---
        ull sa2[4][4];
        #pragma unroll
        for (int i = 0; i < 4; i++)
            #pragma unroll
            for (int j = 0; j < 4; j++) sa2[i][j] = 0ULL;

        for (int c = 0; c < 3; c++) {
            // Stage K chunk duplicated: k_dup[d][2s] = (k,k)
            {
                const int s  = tid & 63;
                const int dg = tid >> 6;     // 0..3 -> dims dg*16 .. +15
                const float* src = &Kg[(size_t)(sbase + s) * DQK + c * 64 + dg * 16];
                #pragma unroll
                for (int g = 0; g < 4; g++) {
                    float4 v4 = *(const float4*)(src + g * 4);
                    int d = dg * 16 + g * 4;
                    ull p0, p1, p2, p3;
                    PACK2(p0, v4.x, v4.x); PACK2(p1, v4.y, v4.y);
                    PACK2(p2, v4.z, v4.z); PACK2(p3, v4.w, v4.w);
                    *(ull*)&k_dup[(d + 0) * 130 + 2 * s] = p0;
                    *(ull*)&k_dup[(d + 1) * 130 + 2 * s] = p1;
                    *(ull*)&k_dup[(d + 2) * 130 + 2 * s] = p2;
                    *(ull*)&k_dup[(d + 3) * 130 + 2 * s] = p3;
                }
            }
            __syncthreads();

            const float* qb = q_t + c * 64 * 128 + ty * 8;
            const float* kb = k_dup + 2 * tx;
            #pragma unroll 4
            for (int d = 0; d < 64; d++) {
                const float* kr = kb + d * 130;
                ull k0 = *(const ull*)(kr);
                ull k1 = *(const ull*)(kr + 32);
                ull k2 = *(const ull*)(kr + 64);
                ull k3 = *(const ull*)(kr + 96);
                ulonglong2 qv = *(const ulonglong2*)(qb + d * 128);      // rows (0,1),(2,3)
                ulonglong2 qw = *(const ulonglong2*)(qb + d * 128 + 4);  // rows (4,5),(6,7)
                FMA2(sa2[0][0], qv.x, k0); FMA2(sa2[0][1], qv.x, k1);
                FMA2(sa2[0][2], qv.x, k2); FMA2(sa2[0][3], qv.x, k3);
                FMA2(sa2[1][0], qv.y, k0); FMA2(sa2[1][1], qv.y, k1);
                FMA2(sa2[1][2], qv.y, k2); FMA2(sa2[1][3], qv.y, k3);
                FMA2(sa2[2][0], qw.x, k0); FMA2(sa2[2][1], qw.x, k1);
                FMA2(sa2[2][2], qw.x, k2); FMA2(sa2[2][3], qw.x, k3);
                FMA2(sa2[3][0], qw.y, k0); FMA2(sa2[3][1], qw.y, k1);
                FMA2(sa2[3][2], qw.y, k2); FMA2(sa2[3][3], qw.y, k3);
            }
            __syncthreads();
        }

        // Write scaled (+masked on diagonal) scores into even slots of P2.
        const bool diag = (tile >= 2 * qt);
        #pragma unroll
        for (int rp = 0; rp < 4; rp++) {
            int r0 = ty * 8 + 2 * rp;
            #pragma unroll
            for (int m = 0; m < 4; m++) {
                float f0, f1;
                UNPACK2(f0, f1, sa2[rp][m]);
                int col = tx + 16 * m;
                f0 *= SCALE_F; f1 *= SCALE_F;
                if (diag) {
                    if (sbase + col > qbase + r0)     f0 = -3.0e38f;
                    if (sbase + col > qbase + r0 + 1) f1 = -3.0e38f;
                }
                P2[(r0    ) * 130 + 2 * col] = f0;
                P2[(r0 + 1) * 130 + 2 * col] = f1;
            }
        }

        // Load V tile (64 x 128), float4
        #pragma unroll
        for (int it = 0; it < 8; it++) {
            int i = tid + it * 256;
            int s = i >> 5, ng = i & 31;
            *(float4*)&v_s[s * 128 + ng * 4] =
                *(const float4*)&Vg[(size_t)(sbase + s) * VD + ng * 4];
        }
        __syncthreads();

        // --- Phase B: online softmax; writes DUPLICATED probs (p,p) ---
        {
            const int r  = tid >> 1;
            const int cg = tid & 1;
            float vals[32];
            float mo = m_s[r];
            float mx = mo;
            #pragma unroll
            for (int jj = 0; jj < 32; jj++) {
                vals[jj] = P2[r * 130 + 2 * (cg + 2 * jj)];
                mx = fmaxf(mx, vals[jj]);
            }
            mx = fmaxf(mx, __shfl_xor_sync(0xffffffffu, mx, 1));
            float scl  = __expf(mo - mx);
            float lsum = 0.0f;
            #pragma unroll
            for (int jj = 0; jj < 32; jj++) {
                float p = __expf(vals[jj] - mx);
                ull pp; PACK2(pp, p, p);
                *(ull*)&P2[r * 130 + 2 * (cg + 2 * jj)] = pp;
                lsum += p;
            }
            lsum += __shfl_xor_sync(0xffffffffu, lsum, 1);
            if (cg == 0) {
                m_s[r]  = mx;
                l_s[r]  = l_s[r] * scl + lsum;
                sc_s[r] = scl;
            }
        }
        __syncthreads();

        // --- Phase C: rescale accumulators, then O += P V (packed) ---
        #pragma unroll
        for (int ii = 0; ii < 8; ii++) {
            float s = sc_s[ty * 8 + ii];
            ull s2; PACK2(s2, s, s);
            MUL2(o2[ii][0], s2); MUL2(o2[ii][1], s2);
            MUL2(o2[ii][2], s2); MUL2(o2[ii][3], s2);
        }
        {
            const float* vb = v_s + 4 * tx;
            const float* pb = P2 + (ty * 8) * 130;
            #pragma unroll 2
            for (int j = 0; j < 64; j++) {
                ulonglong2 vA = *(const ulonglong2*)(vb + j * 128);       // cols 4tx..+3
                ulonglong2 vB = *(const ulonglong2*)(vb + j * 128 + 64);  // cols 64+4tx..+3
                #pragma unroll
                for (int ii = 0; ii < 8; ii++) {
                    ull p2 = *(const ull*)(pb + ii * 130 + 2 * j);        // (p,p)
                    FMA2(o2[ii][0], p2, vA.x); FMA2(o2[ii][1], p2, vA.y);
                    FMA2(o2[ii][2], p2, vB.x); FMA2(o2[ii][3], p2, vB.y);
                }
            }
        }
        __syncthreads();
    }

    // Epilogue: normalize and write (T, H*VD)
    #pragma unroll
    for (int ii = 0; ii < 8; ii++) {
        int t = qbase + ty * 8 + ii;
        float inv = 1.0f / l_s[ty * 8 + ii];
        float a0, a1, a2, a3, a4, a5, a6, a7;
        UNPACK2(a0, a1, o2[ii][0]); UNPACK2(a2, a3, o2[ii][1]);
        UNPACK2(a4, a5, o2[ii][2]); UNPACK2(a6, a7, o2[ii][3]);
        float* dst = &out[(size_t)t * (HH * VD) + h * VD];
        *(float4*)(dst + 4 * tx)      = make_float4(a0*inv, a1*inv, a2*inv, a3*inv);
        *(float4*)(dst + 64 + 4 * tx) = make_float4(a4*inv, a5*inv, a6*inv, a7*inv);
    }
}

// ---------------------------------------------------------------------------
// Launch
// ---------------------------------------------------------------------------
extern "C" void kernel_launch(void* const* d_in, const int* in_sizes, int n_in,
                              void* d_out, int out_size)
{
    const float* query = (const float*)d_in[0];   // (T, H, 192)
    const float* kc    = (const float*)d_in[1];   // (T, 512)
    const float* kpe   = (const float*)d_in[2];   // (T, 64)
    const float* wkv   = (const float*)d_in[3];   // (512, 4096)
    const float* wuv   = (const float*)d_in[4];   // (16, 512, 128)
    float* out         = (float*)d_out;           // (T, 2048)

    // Projections: K (nope+rope) and effective V
    {
        dim3 grid(TT / 64, HH, 2);
        proj_kernel<<<grid, 256>>>(kc, wkv, wuv, kpe);
    }

    // Flash attention (packed f32x2)
    {
        const int smem_bytes = ATTN_SMEM_FLOATS * (int)sizeof(float);  // 232448
        cudaFuncSetAttribute(attn_kernel, cudaFuncAttributeMaxDynamicSharedMemorySize,
                             smem_bytes);
        dim3 grid(TT / 128, HH);
        attn_kernel<<<grid, 256, smem_bytes>>>(query, out);
    }
}

// round 13
// speedup vs baseline: 1.3634x; 1.3634x over previous
#include <cuda_runtime.h>
#include <cuda_bf16.h>
#include <math.h>
#include <stdint.h>

#define TT   2048
#define HH   16
#define DQK  192
#define NOPE 128
#define ROPE 64
#define LORA 512
#define VD   128
#define SCALE_F (0.07216878364870322f)  // 1/sqrt(192)

typedef unsigned int u32;
typedef unsigned long long u64;

// ---------------------------------------------------------------------------
// Device scratch: bf16 two-term splits, produced by proj, consumed by attn.
//   g_Khi/g_Klo : [HH][TT][192]   K = [k_nope | k_pe]
//   g_Vthi/lo   : [HH][128][TT]   V^T (dim-major) -> PV B operand rows
// ---------------------------------------------------------------------------
__device__ __align__(16) __nv_bfloat16 g_Khi[HH * TT * DQK];
__device__ __align__(16) __nv_bfloat16 g_Klo[HH * TT * DQK];
__device__ __align__(16) __nv_bfloat16 g_Vthi[HH * VD * TT];
__device__ __align__(16) __nv_bfloat16 g_Vtlo[HH * VD * TT];

// ---------------------------------------------------------------------------
// Helpers (all arch-agnostic PTX: mma.sync / ldmatrix / cp.async, sm_80+)
// ---------------------------------------------------------------------------
__device__ __forceinline__ u32 smem_u32(const void* p) {
    u32 a;
    asm("{ .reg .u64 t; cvta.to.shared.u64 t, %1; cvt.u32.u64 %0, t; }" : "=r"(a) : "l"(p));
    return a;
}

#define LDSM4(r0, r1, r2, r3, addr) \
    asm volatile("ldmatrix.sync.aligned.m8n8.x4.shared.b16 {%0,%1,%2,%3}, [%4];" \
        : "=r"(r0), "=r"(r1), "=r"(r2), "=r"(r3) : "r"(addr))

#define MMA16816(c, a, b0, b1) \
    asm volatile("mma.sync.aligned.m16n8k16.row.col.f32.bf16.bf16.f32 " \
        "{%0,%1,%2,%3}, {%4,%5,%6,%7}, {%8,%9}, {%0,%1,%2,%3};" \
        : "+f"((c)[0]), "+f"((c)[1]), "+f"((c)[2]), "+f"((c)[3]) \
        : "r"((a)[0]), "r"((a)[1]), "r"((a)[2]), "r"((a)[3]), "r"(b0), "r"(b1))

#define CP_ASYNC16(dst_u32, src_ptr) \
    asm volatile("cp.async.cg.shared.global [%0], [%1], 16;" :: "r"(dst_u32), "l"(src_ptr))
#define CP_COMMIT() asm volatile("cp.async.commit_group;" ::: "memory")
#define CP_WAIT1()  asm volatile("cp.async.wait_group 1;" ::: "memory")
#define CP_WAIT0()  asm volatile("cp.async.wait_group 0;" ::: "memory")

// Two-term bf16 split of a float pair, packed as bf16x2 (low half = first elem)
__device__ __forceinline__ void bsplit2(float a, float b, u32& hi, u32& lo) {
    __nv_bfloat16 ah = __float2bfloat16(a), bh = __float2bfloat16(b);
    float ar = a - __bfloat162float(ah);
    float br = b - __bfloat162float(bh);
    __nv_bfloat162 H; H.x = ah; H.y = bh;
    __nv_bfloat162 L; L.x = __float2bfloat16(ar); L.y = __float2bfloat16(br);
    hi = *(u32*)&H; lo = *(u32*)&L;
}
__device__ __forceinline__ void bsplit1(float x, __nv_bfloat16& hi, __nv_bfloat16& lo) {
    hi = __float2bfloat16(x);
    lo = __float2bfloat16(x - __bfloat162float(hi));
}

// ---------------------------------------------------------------------------
// Projection kernel (R8 fp32 GEMM core; bf16 hi/lo split outputs)
//   z==0 -> g_Khi/lo [h][t][192] ; z==1 -> g_Vthi/lo [h][n][t]
// ---------------------------------------------------------------------------
__global__ __launch_bounds__(256)
void proj_kernel(const float* __restrict__ kc, const float* __restrict__ wkv,
                 const float* __restrict__ wuv, const float* __restrict__ kpe)
{
    const int rbase = blockIdx.x * 64;
    const int h     = blockIdx.y;
    const int which = blockIdx.z;

    __shared__ float a_s[32 * 68];
    __shared__ float b_s[32 * 132];

    const int tid = threadIdx.x;
    const int ty  = tid >> 4;
    const int tx  = tid & 15;

    float acc[4][8];
    #pragma unroll
    for (int i = 0; i < 4; i++)
        #pragma unroll
        for (int j = 0; j < 8; j++) acc[i][j] = 0.0f;

    const float* Bp      = (which == 0) ? (wkv + h * 256) : (wuv + (size_t)h * LORA * VD);
    const int    bstride = (which == 0) ? (HH * 256) : VD;

    for (int lc = 0; lc < LORA; lc += 32) {
        #pragma unroll
        for (int i = tid; i < 64 * 32; i += 256) {
            int row = i >> 5, l = i & 31;
            a_s[l * 68 + row] = kc[(rbase + row) * LORA + lc + l];
        }
        #pragma unroll
        for (int i = tid; i < 32 * 128; i += 256) {
            int l = i >> 7, n = i & 127;
            b_s[l * 132 + n] = Bp[(size_t)(lc + l) * bstride + n];
        }
        __syncthreads();

        #pragma unroll
        for (int kk = 0; kk < 32; kk++) {
            float4 a4 = *(const float4*)&a_s[kk * 68 + ty * 4];
            float4 b0 = *(const float4*)&b_s[kk * 132 + tx * 8];
            float4 b1 = *(const float4*)&b_s[kk * 132 + tx * 8 + 4];
            float av[4] = {a4.x, a4.y, a4.z, a4.w};
            float bv[8] = {b0.x, b0.y, b0.z, b0.w, b1.x, b1.y, b1.z, b1.w};
            #pragma unroll
            for (int ii = 0; ii < 4; ii++)
                #pragma unroll
                for (int jj = 0; jj < 8; jj++)
                    acc[ii][jj] += av[ii] * bv[jj];
        }
        __syncthreads();
    }

    if (which == 0) {
        #pragma unroll
        for (int ii = 0; ii < 4; ii++) {
            int t = rbase + ty * 4 + ii;
            size_t base = ((size_t)h * TT + t) * DQK + tx * 8;
            #pragma unroll
            for (int g = 0; g < 4; g++) {
                u32 hi, lo;
                bsplit2(acc[ii][2 * g], acc[ii][2 * g + 1], hi, lo);
                *(u32*)&g_Khi[base + 2 * g] = hi;
                *(u32*)&g_Klo[base + 2 * g] = lo;
            }
        }
        // RoPE tail: dims 128..191
        #pragma unroll
        for (int i = tid; i < 64 * 32; i += 256) {
            int row = i >> 5, dp = i & 31;
            size_t base = ((size_t)h * TT + rbase + row) * DQK + NOPE + 2 * dp;
            float v0 = kpe[(rbase + row) * ROPE + 2 * dp];
            float v1 = kpe[(rbase + row) * ROPE + 2 * dp + 1];
            u32 hi, lo; bsplit2(v0, v1, hi, lo);
            *(u32*)&g_Khi[base] = hi;
            *(u32*)&g_Klo[base] = lo;
        }
    } else {
        // V^T: pack 4 consecutive t (ii=0..3) per 8B store
        int t0 = rbase + ty * 4;
        #pragma unroll
        for (int jj = 0; jj < 8; jj++) {
            int n = tx * 8 + jj;
            __nv_bfloat16 h4[4], l4[4];
            #pragma unroll
            for (int ii = 0; ii < 4; ii++) bsplit1(acc[ii][jj], h4[ii], l4[ii]);
            size_t idx = ((size_t)h * VD + n) * TT + t0;
            *(u64*)&g_Vthi[idx] = *(u64*)h4;
            *(u64*)&g_Vtlo[idx] = *(u64*)l4;
        }
    }
}

// ---------------------------------------------------------------------------
// mma.sync flash attention: 128q x 64k tiles, bf16 2-term split (3 MMAs).
// 8 warps; warp w owns rows 16w..16w+15 (softmax fully warp-local).
// smem per buffer: Kh 24576 | Kl 24576 | Vh 16384 | Vl 16384 = 81920 B, x2.
// ---------------------------------------------------------------------------
#define KH_OFF 0
#define KL_OFF 24576
#define VH_OFF 49152
#define VL_OFF 65536
#define BUFSZ  81920
#define ATTN_SMEM (2 * BUFSZ)

__device__ __forceinline__ void stage_tile(
    int tid, u32 sb, u32 bufoff, int kb,
    const __nv_bfloat16* Kh, const __nv_bfloat16* Kl,
    const __nv_bfloat16* Vh, const __nv_bfloat16* Vl)
{
    // K: 64 rows x 24 16B-chunks (192 bf16), XOR swizzle chunk^(row&7)
    #pragma unroll
    for (int i = tid; i < 1536; i += 256) {
        int row = i / 24, c = i % 24;
        u32 dst = sb + bufoff + row * 384 + (u32)((c ^ (row & 7)) << 4);
        size_t src = (size_t)(kb + row) * DQK + c * 8;
        CP_ASYNC16(dst + KH_OFF, (const char*)(Kh + src));
        CP_ASYNC16(dst + KL_OFF, (const char*)(Kl + src));
    }
    // V^T: 128 rows (dims) x 8 chunks (64 keys)
    #pragma unroll
    for (int i = tid; i < 1024; i += 256) {
        int row = i >> 3, c = i & 7;
        u32 dst = sb + bufoff + row * 128 + (u32)((c ^ (row & 7)) << 4);
        size_t src = (size_t)row * TT + kb + c * 8;
        CP_ASYNC16(dst + VH_OFF, (const char*)(Vh + src));
        CP_ASYNC16(dst + VL_OFF, (const char*)(Vl + src));
    }
}

__global__ __launch_bounds__(256, 1)
void attn_kernel(const float* __restrict__ q, float* __restrict__ out)
{
    extern __shared__ char smem[];
    const u32 sb = smem_u32(smem);

    const int h     = blockIdx.y;
    const int qt    = (int)gridDim.x - 1 - (int)blockIdx.x;  // big tiles first
    const int qbase = qt * 128;
    const int tid   = threadIdx.x;
    const int w     = tid >> 5;
    const int lane  = tid & 31;
    const int g     = lane >> 2;          // row-in-fragment
    const int t2    = (lane & 3) * 2;     // col pair base
    const int quad  = lane >> 3;
    const int lrow  = lane & 7;
    const int row0  = qbase + 16 * w + g; // this thread's first query row

    // --- Q fragments (persistent, gathered once): 12 k-steps, hi & lo ---
    u32 qh[12][4], ql[12][4];
    {
        const float* q0 = q + ((size_t)row0 * HH + h) * DQK;
        const float* q8 = q0 + (size_t)8 * HH * DQK;
        #pragma unroll
        for (int ks = 0; ks < 12; ks++) {
            int k0 = 16 * ks + t2;
            float2 v0 = *(const float2*)(q0 + k0);
            float2 v1 = *(const float2*)(q8 + k0);
            float2 v2 = *(const float2*)(q0 + k0 + 8);
            float2 v3 = *(const float2*)(q8 + k0 + 8);
            bsplit2(v0.x, v0.y, qh[ks][0], ql[ks][0]);
            bsplit2(v1.x, v1.y, qh[ks][1], ql[ks][1]);
            bsplit2(v2.x, v2.y, qh[ks][2], ql[ks][2]);
            bsplit2(v3.x, v3.y, qh[ks][3], ql[ks][3]);
        }
    }

    float oa[16][4];
    #pragma unroll
    for (int i = 0; i < 16; i++)
        #pragma unroll
        for (int j = 0; j < 4; j++) oa[i][j] = 0.0f;
    float m0 = -3.0e38f, m1 = -3.0e38f, l0 = 0.0f, l1 = 0.0f;

    const __nv_bfloat16* KhP = g_Khi  + (size_t)h * TT * DQK;
    const __nv_bfloat16* KlP = g_Klo  + (size_t)h * TT * DQK;
    const __nv_bfloat16* VhP = g_Vthi + (size_t)h * VD * TT;
    const __nv_bfloat16* VlP = g_Vtlo + (size_t)h * VD * TT;

    const int nt = 2 * qt + 2;

    stage_tile(tid, sb, 0, 0, KhP, KlP, VhP, VlP);
    CP_COMMIT();

    for (int tile = 0; tile < nt; tile++) {
        const u32 B = (tile & 1) ? (u32)BUFSZ : 0u;
        if (tile + 1 < nt) {
            stage_tile(tid, sb, (tile & 1) ? 0u : (u32)BUFSZ, 64 * (tile + 1),
                       KhP, KlP, VhP, VlP);
            CP_COMMIT();
            CP_WAIT1();
        } else {
            CP_WAIT0();
        }
        __syncthreads();

        // --- QK: S = (Qh+Ql)(Kh+Kl)^T, warp rows 16w..+15, cols 0..63 ---
        float sa[8][4];
        #pragma unroll
        for (int i = 0; i < 8; i++)
            #pragma unroll
            for (int j = 0; j < 4; j++) sa[i][j] = 0.0f;

        const u32 kh_b = sb + B + KH_OFF;
        const u32 kl_b = sb + B + KL_OFF;
        #pragma unroll
        for (int na = 0; na < 8; na++) {
            const int rw = na * 8 + lrow;
            const u32 rbase2 = (u32)(rw * 384);
            #pragma unroll
            for (int ks2 = 0; ks2 < 6; ks2++) {
                const u32 coff = (u32)((((4 * ks2 + quad) ^ (rw & 7))) << 4);
                u32 r0, r1, r2, r3;
                LDSM4(r0, r1, r2, r3, kh_b + rbase2 + coff);
                MMA16816(sa[na], qh[2 * ks2],     r0, r1);
                MMA16816(sa[na], qh[2 * ks2 + 1], r2, r3);
                MMA16816(sa[na], ql[2 * ks2],     r0, r1);
                MMA16816(sa[na], ql[2 * ks2 + 1], r2, r3);
                u32 s0, s1, s2, s3;
                LDSM4(s0, s1, s2, s3, kl_b + rbase2 + coff);
                MMA16816(sa[na], qh[2 * ks2],     s0, s1);
                MMA16816(sa[na], qh[2 * ks2 + 1], s2, s3);
            }
        }

        // --- scale + mask + warp-local online softmax ---
        const int kb = 64 * tile;
        const bool diag = (tile >= 2 * qt);
        float mx0 = -3.0e38f, mx1 = -3.0e38f;
        #pragma unroll
        for (int na = 0; na < 8; na++) {
            const int c = kb + 8 * na + t2;
            sa[na][0] *= SCALE_F; sa[na][1] *= SCALE_F;
            sa[na][2] *= SCALE_F; sa[na][3] *= SCALE_F;
            if (diag) {
                if (c     > row0)     sa[na][0] = -1.0e30f;
                if (c + 1 > row0)     sa[na][1] = -1.0e30f;
                if (c     > row0 + 8) sa[na][2] = -1.0e30f;
                if (c + 1 > row0 + 8) sa[na][3] = -1.0e30f;
            }
            mx0 = fmaxf(mx0, fmaxf(sa[na][0], sa[na][1]));
            mx1 = fmaxf(mx1, fmaxf(sa[na][2], sa[na][3]));
        }
        mx0 = fmaxf(mx0, __shfl_xor_sync(0xffffffffu, mx0, 1));
        mx0 = fmaxf(mx0, __shfl_xor_sync(0xffffffffu, mx0, 2));
        mx1 = fmaxf(mx1, __shfl_xor_sync(0xffffffffu, mx1, 1));
        mx1 = fmaxf(mx1, __shfl_xor_sync(0xffffffffu, mx1, 2));
        const float mn0 = fmaxf(m0, mx0), mn1 = fmaxf(m1, mx1);
        const float sc0 = __expf(m0 - mn0), sc1 = __expf(m1 - mn1);
        m0 = mn0; m1 = mn1;

        float sum0 = 0.0f, sum1 = 0.0f;
        #pragma unroll
        for (int na = 0; na < 8; na++) {
            sa[na][0] = __expf(sa[na][0] - mn0);
            sa[na][1] = __expf(sa[na][1] - mn0);
            sa[na][2] = __expf(sa[na][2] - mn1);
            sa[na][3] = __expf(sa[na][3] - mn1);
            sum0 += sa[na][0] + sa[na][1];
            sum1 += sa[na][2] + sa[na][3];
        }
        sum0 += __shfl_xor_sync(0xffffffffu, sum0, 1);
        sum0 += __shfl_xor_sync(0xffffffffu, sum0, 2);
        sum1 += __shfl_xor_sync(0xffffffffu, sum1, 1);
        sum1 += __shfl_xor_sync(0xffffffffu, sum1, 2);
        l0 = l0 * sc0 + sum0;
        l1 = l1 * sc1 + sum1;

        // --- P: C-frag -> A-frag repack + bf16 split (registers only) ---
        u32 ph[4][4], pl[4][4];
        #pragma unroll
        for (int ks = 0; ks < 4; ks++) {
            bsplit2(sa[2 * ks][0],     sa[2 * ks][1],     ph[ks][0], pl[ks][0]);
            bsplit2(sa[2 * ks][2],     sa[2 * ks][3],     ph[ks][1], pl[ks][1]);
            bsplit2(sa[2 * ks + 1][0], sa[2 * ks + 1][1], ph[ks][2], pl[ks][2]);
            bsplit2(sa[2 * ks + 1][2], sa[2 * ks + 1][3], ph[ks][3], pl[ks][3]);
        }

        // --- rescale O, then O += (Ph+Pl)(Vh+Vl) ---
        #pragma unroll
        for (int na = 0; na < 16; na++) {
            oa[na][0] *= sc0; oa[na][1] *= sc0;
            oa[na][2] *= sc1; oa[na][3] *= sc1;
        }
        const u32 vh_b = sb + B + VH_OFF;
        const u32 vl_b = sb + B + VL_OFF;
        #pragma unroll
        for (int na = 0; na < 16; na++) {
            const int rw = na * 8 + lrow;
            const u32 rbase2 = (u32)(rw * 128);
            #pragma unroll
            for (int ks2 = 0; ks2 < 2; ks2++) {
                const u32 coff = (u32)((((4 * ks2 + quad) ^ (rw & 7))) << 4);
                u32 r0, r1, r2, r3;
                LDSM4(r0, r1, r2, r3, vh_b + rbase2 + coff);
                MMA16816(oa[na], ph[2 * ks2],     r0, r1);
                MMA16816(oa[na], ph[2 * ks2 + 1], r2, r3);
                MMA16816(oa[na], pl[2 * ks2],     r0, r1);
                MMA16816(oa[na], pl[2 * ks2 + 1], r2, r3);
                u32 s0, s1, s2, s3;
                LDSM4(s0, s1, s2, s3, vl_b + rbase2 + coff);
                MMA16816(oa[na], ph[2 * ks2],     s0, s1);
                MMA16816(oa[na], ph[2 * ks2 + 1], s2, s3);
            }
        }
        __syncthreads();
    }

    // --- Epilogue: normalize, write rows row0 and row0+8 ---
    const float i0 = 1.0f / l0, i1 = 1.0f / l1;
    float* d0 = out + (size_t)row0 * (HH * VD) + h * VD;
    float* d8 = d0 + (size_t)8 * HH * VD;
    #pragma unroll
    for (int na = 0; na < 16; na++) {
        *(float2*)(d0 + 8 * na + t2) = make_float2(oa[na][0] * i0, oa[na][1] * i0);
        *(float2*)(d8 + 8 * na + t2) = make_float2(oa[na][2] * i1, oa[na][3] * i1);
    }
}

// ---------------------------------------------------------------------------
// Launch
// ---------------------------------------------------------------------------
extern "C" void kernel_launch(void* const* d_in, const int* in_sizes, int n_in,
                              void* d_out, int out_size)
{
    const float* query = (const float*)d_in[0];   // (T, H, 192)
    const float* kc    = (const float*)d_in[1];   // (T, 512)
    const float* kpe   = (const float*)d_in[2];   // (T, 64)
    const float* wkv   = (const float*)d_in[3];   // (512, 4096)
    const float* wuv   = (const float*)d_in[4];   // (16, 512, 128)
    float* out         = (float*)d_out;           // (T, 2048)

    {
        dim3 grid(TT / 64, HH, 2);
        proj_kernel<<<grid, 256>>>(kc, wkv, wuv, kpe);
    }
    {
        cudaFuncSetAttribute(attn_kernel, cudaFuncAttributeMaxDynamicSharedMemorySize,
                             ATTN_SMEM);
        dim3 grid(TT / 128, HH);
        attn_kernel<<<grid, 256, ATTN_SMEM>>>(query, out);
    }
}

// round 14
// speedup vs baseline: 3.1827x; 2.3344x over previous
#include <cuda_runtime.h>
#include <cuda_bf16.h>
#include <math.h>
#include <stdint.h>

#define TT   2048
#define HH   16
#define DQK  192
#define NOPE 128
#define ROPE 64
#define LORA 512
#define VD   128
#define SCALE_F (0.07216878364870322f)  // 1/sqrt(192)

typedef unsigned int u32;
typedef unsigned long long u64;

// ---------------------------------------------------------------------------
// Device scratch
// ---------------------------------------------------------------------------
__device__ __align__(16) __nv_bfloat16 g_Khi[HH * TT * DQK];   // [h][t][192]
__device__ __align__(16) __nv_bfloat16 g_Klo[HH * TT * DQK];
__device__ __align__(16) __nv_bfloat16 g_Vthi[HH * VD * TT];   // [h][n][t]
__device__ __align__(16) __nv_bfloat16 g_Vtlo[HH * VD * TT];
__device__ __align__(16) __nv_bfloat16 g_KChi[TT * LORA];      // A operand [t][l]
__device__ __align__(16) __nv_bfloat16 g_KClo[TT * LORA];
__device__ __align__(16) __nv_bfloat16 g_Wthi[4096 * LORA];    // B operand [n][l]
__device__ __align__(16) __nv_bfloat16 g_Wtlo[4096 * LORA];

// ---------------------------------------------------------------------------
// Helpers (arch-agnostic PTX only: mma.sync / ldmatrix / cp.async)
// ---------------------------------------------------------------------------
__device__ __forceinline__ u32 smem_u32(const void* p) {
    u32 a;
    asm("{ .reg .u64 t; cvta.to.shared.u64 t, %1; cvt.u32.u64 %0, t; }" : "=r"(a) : "l"(p));
    return a;
}

#define LDSM4(r0, r1, r2, r3, addr) \
    asm volatile("ldmatrix.sync.aligned.m8n8.x4.shared.b16 {%0,%1,%2,%3}, [%4];" \
        : "=r"(r0), "=r"(r1), "=r"(r2), "=r"(r3) : "r"(addr))

#define MMA16816(c, a, b0, b1) \
    asm volatile("mma.sync.aligned.m16n8k16.row.col.f32.bf16.bf16.f32 " \
        "{%0,%1,%2,%3}, {%4,%5,%6,%7}, {%8,%9}, {%0,%1,%2,%3};" \
        : "+f"((c)[0]), "+f"((c)[1]), "+f"((c)[2]), "+f"((c)[3]) \
        : "r"((a)[0]), "r"((a)[1]), "r"((a)[2]), "r"((a)[3]), "r"(b0), "r"(b1))

#define CP_ASYNC16(dst_u32, src_ptr) \
    asm volatile("cp.async.cg.shared.global [%0], [%1], 16;" :: "r"(dst_u32), "l"(src_ptr))
#define CP_COMMIT() asm volatile("cp.async.commit_group;" ::: "memory")
#define CP_WAIT1()  asm volatile("cp.async.wait_group 1;" ::: "memory")
#define CP_WAIT0()  asm volatile("cp.async.wait_group 0;" ::: "memory")

__device__ __forceinline__ void bsplit2(float a, float b, u32& hi, u32& lo) {
    __nv_bfloat16 ah = __float2bfloat16(a), bh = __float2bfloat16(b);
    float ar = a - __bfloat162float(ah);
    float br = b - __bfloat162float(bh);
    __nv_bfloat162 H; H.x = ah; H.y = bh;
    __nv_bfloat162 L; L.x = __float2bfloat16(ar); L.y = __float2bfloat16(br);
    hi = *(u32*)&H; lo = *(u32*)&L;
}
__device__ __forceinline__ void bsplit1(float x, __nv_bfloat16& hi, __nv_bfloat16& lo) {
    hi = __float2bfloat16(x);
    lo = __float2bfloat16(x - __bfloat162float(hi));
}

// ---------------------------------------------------------------------------
// Convert kernels (one-shot, memory-bound)
// ---------------------------------------------------------------------------
__global__ __launch_bounds__(256)
void conv_kc(const float* __restrict__ kc)
{
    int idx = blockIdx.x * 256 + threadIdx.x;          // over T*LORA/2
    if (idx >= TT * LORA / 2) return;
    float2 v = ((const float2*)kc)[idx];
    u32 hi, lo; bsplit2(v.x, v.y, hi, lo);
    ((u32*)g_KChi)[idx] = hi;
    ((u32*)g_KClo)[idx] = lo;
}

__global__ __launch_bounds__(256)
void conv_rope(const float* __restrict__ kpe)
{
    int idx = blockIdx.x * 256 + threadIdx.x;          // over HH*TT*32 pairs
    if (idx >= HH * TT * 32) return;
    int h = idx >> 16;            // TT*32 = 65536
    int rem = idx & 65535;
    int t = rem >> 5, dp = rem & 31;
    float2 v = *(const float2*)(kpe + t * ROPE + 2 * dp);
    u32 hi, lo; bsplit2(v.x, v.y, hi, lo);
    size_t base = ((size_t)h * TT + t) * DQK + NOPE + 2 * dp;
    *(u32*)&g_Khi[base] = hi;
    *(u32*)&g_Klo[base] = lo;
}

// Combined transposed weights: rows n<2048 -> K-nope col (h*256+d of w_kv_b),
// rows n>=2048 -> V col (w_uv[h][:,vd]).  Layout [n][l] so B frags come from
// non-trans ldmatrix exactly like attn's K tiles.
__global__ __launch_bounds__(256)
void conv_w(const float* __restrict__ wkv, const float* __restrict__ wuv)
{
    int idx = blockIdx.x * 256 + threadIdx.x;          // over 4096*128
    if (idx >= 4096 * 128) return;
    int n = idx >> 7, lq = idx & 127;
    int l0 = lq * 4;
    float v[4];
    if (n < 2048) {
        int h = n >> 7, d = n & 127;
        const float* s = wkv + (size_t)l0 * 4096 + h * 256 + d;
        v[0] = s[0]; v[1] = s[4096]; v[2] = s[8192]; v[3] = s[12288];
    } else {
        int h = (n - 2048) >> 7, vd = n & 127;
        const float* s = wuv + ((size_t)h * LORA + l0) * VD + vd;
        v[0] = s[0]; v[1] = s[128]; v[2] = s[256]; v[3] = s[384];
    }
    __nv_bfloat16 h4[4], l4[4];
    #pragma unroll
    for (int i = 0; i < 4; i++) bsplit1(v[i], h4[i], l4[i]);
    size_t o = (size_t)n * LORA + l0;
    *(u64*)&g_Wthi[o] = *(u64*)h4;
    *(u64*)&g_Wtlo[o] = *(u64*)l4;
}

// ---------------------------------------------------------------------------
// Tensor-core projection GEMM: C[2048 x 4096] = kc[2048 x 512] @ Wt^T.
// 128x128 tiles, k in 8 double-buffered chunks of 64, bf16 3-term split.
// by<16 -> K output [h][t][d] ; by>=16 -> V output via smem transpose [h][n][t].
// ---------------------------------------------------------------------------
#define PA_H 0
#define PA_L 16384
#define PB_H 32768
#define PB_L 49152
#define PBUF 65536
#define PROJ_SMEM (2 * PBUF)   // 131072 B

__global__ __launch_bounds__(256, 1)
void proj_mma()
{
    extern __shared__ char smem[];
    const u32 sb = smem_u32(smem);

    const int bx = blockIdx.x;          // t tile (16)
    const int by = blockIdx.y;          // col tile (32)
    const int tbase = bx * 128, nbase = by * 128;
    const int tid  = threadIdx.x;
    const int w    = tid >> 5, lane = tid & 31;
    const int wm   = w & 1, wn = w >> 1;       // 2 x 4 warp grid (64m x 32n each)
    const int g    = lane >> 2, t2 = (lane & 3) * 2;
    const int quad = lane >> 3, lrow = lane & 7;

    float acc[4][4][4];
    #pragma unroll
    for (int i = 0; i < 4; i++)
        #pragma unroll
        for (int j = 0; j < 4; j++)
            #pragma unroll
            for (int k = 0; k < 4; k++) acc[i][j][k] = 0.0f;

    // --- staging: A rows = t, B rows = n; both [row][64] bf16, 8 chunks ---
    #define PROJ_STAGE(bo, kc_)                                                   \
        do {                                                                      \
            _Pragma("unroll")                                                     \
            for (int i = tid; i < 1024; i += 256) {                               \
                int row = i >> 3, c = i & 7;                                      \
                u32 off = (u32)(row * 128 + ((c ^ (row & 7)) << 4));              \
                size_t as = (size_t)(tbase + row) * LORA + (kc_) + c * 8;         \
                CP_ASYNC16(sb + (bo) + PA_H + off, (const char*)(g_KChi + as));   \
                CP_ASYNC16(sb + (bo) + PA_L + off, (const char*)(g_KClo + as));   \
                size_t bs = (size_t)(nbase + row) * LORA + (kc_) + c * 8;         \
                CP_ASYNC16(sb + (bo) + PB_H + off, (const char*)(g_Wthi + bs));   \
                CP_ASYNC16(sb + (bo) + PB_L + off, (const char*)(g_Wtlo + bs));   \
            }                                                                     \
        } while (0)

    PROJ_STAGE(0u, 0);
    CP_COMMIT();

    for (int kc = 0; kc < 8; kc++) {
        const u32 B = (kc & 1) ? (u32)PBUF : 0u;
        if (kc + 1 < 8) {
            PROJ_STAGE((kc & 1) ? 0u : (u32)PBUF, (kc + 1) * 64);
            CP_COMMIT();
            CP_WAIT1();
        } else {
            CP_WAIT0();
        }
        __syncthreads();

        #pragma unroll
        for (int ks2 = 0; ks2 < 2; ks2++) {        // 2 x (32 k)
            // B fragments: 4 n-blocks, 4 chunks each (= 2 k-steps)
            u32 bh[4][4], bl[4][4];
            #pragma unroll
            for (int nb = 0; nb < 4; nb++) {
                int row = wn * 32 + nb * 8 + lrow;
                u32 off = (u32)(row * 128 + (((4 * ks2 + quad) ^ (row & 7)) << 4));
                LDSM4(bh[nb][0], bh[nb][1], bh[nb][2], bh[nb][3], sb + B + PB_H + off);
                LDSM4(bl[nb][0], bl[nb][1], bl[nb][2], bl[nb][3], sb + B + PB_L + off);
            }
            // A fragments: 4 m-blocks x 2 k-steps
            u32 ah[4][2][4], al[4][2][4];
            #pragma unroll
            for (int mb = 0; mb < 4; mb++) {
                int row = wm * 64 + mb * 16 + ((lane >> 3) & 1) * 8 + (lane & 7);
                #pragma unroll
                for (int kst = 0; kst < 2; kst++) {
                    int ch = 2 * (2 * ks2 + kst) + (lane >> 4);
                    u32 off = (u32)(row * 128 + ((ch ^ (row & 7)) << 4));
                    LDSM4(ah[mb][kst][0], ah[mb][kst][1], ah[mb][kst][2], ah[mb][kst][3],
                          sb + B + PA_H + off);
                    LDSM4(al[mb][kst][0], al[mb][kst][1], al[mb][kst][2], al[mb][kst][3],
                          sb + B + PA_L + off);
                }
            }
            // MMAs: 2 kst x 4 nb x 4 mb x 3 terms = 96
            #pragma unroll
            for (int kst = 0; kst < 2; kst++)
                #pragma unroll
                for (int nb = 0; nb < 4; nb++) {
                    u32 b0h = bh[nb][2 * kst], b1h = bh[nb][2 * kst + 1];
                    u32 b0l = bl[nb][2 * kst], b1l = bl[nb][2 * kst + 1];
                    #pragma unroll
                    for (int mb = 0; mb < 4; mb++) {
                        MMA16816(acc[mb][nb], ah[mb][kst], b0h, b1h);
                        MMA16816(acc[mb][nb], al[mb][kst], b0h, b1h);
                        MMA16816(acc[mb][nb], ah[mb][kst], b0l, b1l);
                    }
                }
        }
        __syncthreads();
    }

    // --- Epilogue ---
    if (by < 16) {
        // K output: h = by, d = col (0..127 all < NOPE)
        const int h = by;
        #pragma unroll
        for (int mb = 0; mb < 4; mb++) {
            int t = tbase + wm * 64 + mb * 16 + g;
            #pragma unroll
            for (int nb = 0; nb < 4; nb++) {
                int d = wn * 32 + nb * 8 + t2;
                u32 hi, lo;
                bsplit2(acc[mb][nb][0], acc[mb][nb][1], hi, lo);
                size_t o = ((size_t)h * TT + t) * DQK + d;
                *(u32*)&g_Khi[o] = hi;  *(u32*)&g_Klo[o] = lo;
                bsplit2(acc[mb][nb][2], acc[mb][nb][3], hi, lo);
                o += (size_t)8 * DQK;
                *(u32*)&g_Khi[o] = hi;  *(u32*)&g_Klo[o] = lo;
            }
        }
    } else {
        // V output: bounce through smem, write transposed [h][n][t] packed by t
        const int h = by - 16;
        float* c_s = (float*)smem;     // 128 x 132 floats = 67.5 KB (reuse buffers)
        #pragma unroll
        for (int mb = 0; mb < 4; mb++) {
            int r = wm * 64 + mb * 16 + g;
            #pragma unroll
            for (int nb = 0; nb < 4; nb++) {
                int c = wn * 32 + nb * 8 + t2;
                *(float2*)&c_s[r * 132 + c]       = make_float2(acc[mb][nb][0], acc[mb][nb][1]);
                *(float2*)&c_s[(r + 8) * 132 + c] = make_float2(acc[mb][nb][2], acc[mb][nb][3]);
            }
        }
        __syncthreads();
        #pragma unroll
        for (int i = tid; i < 4096; i += 256) {
            int n = i >> 5, tg = i & 31;
            int t0 = tg * 4;
            __nv_bfloat16 h4[4], l4[4];
            #pragma unroll
            for (int j = 0; j < 4; j++)
                bsplit1(c_s[(t0 + j) * 132 + n], h4[j], l4[j]);
            size_t o = ((size_t)h * VD + n) * TT + tbase + t0;
            *(u64*)&g_Vthi[o] = *(u64*)h4;
            *(u64*)&g_Vtlo[o] = *(u64*)l4;
        }
    }
}

// ---------------------------------------------------------------------------
// mma.sync flash attention (unchanged from R13 — regs at cap, tensor-bound)
// ---------------------------------------------------------------------------
#define KH_OFF 0
#define KL_OFF 24576
#define VH_OFF 49152
#define VL_OFF 65536
#define BUFSZ  81920
#define ATTN_SMEM (2 * BUFSZ)

__device__ __forceinline__ void stage_tile(
    int tid, u32 sb, u32 bufoff, int kb,
    const __nv_bfloat16* Kh, const __nv_bfloat16* Kl,
    const __nv_bfloat16* Vh, const __nv_bfloat16* Vl)
{
    #pragma unroll
    for (int i = tid; i < 1536; i += 256) {
        int row = i / 24, c = i % 24;
        u32 dst = sb + bufoff + row * 384 + (u32)((c ^ (row & 7)) << 4);
        size_t src = (size_t)(kb + row) * DQK + c * 8;
        CP_ASYNC16(dst + KH_OFF, (const char*)(Kh + src));
        CP_ASYNC16(dst + KL_OFF, (const char*)(Kl + src));
    }
    #pragma unroll
    for (int i = tid; i < 1024; i += 256) {
        int row = i >> 3, c = i & 7;
        u32 dst = sb + bufoff + row * 128 + (u32)((c ^ (row & 7)) << 4);
        size_t src = (size_t)row * TT + kb + c * 8;
        CP_ASYNC16(dst + VH_OFF, (const char*)(Vh + src));
        CP_ASYNC16(dst + VL_OFF, (const char*)(Vl + src));
    }
}

__global__ __launch_bounds__(256, 1)
void attn_kernel(const float* __restrict__ q, float* __restrict__ out)
{
    extern __shared__ char smem[];
    const u32 sb = smem_u32(smem);

    const int h     = blockIdx.y;
    const int qt    = (int)gridDim.x - 1 - (int)blockIdx.x;
    const int qbase = qt * 128;
    const int tid   = threadIdx.x;
    const int w     = tid >> 5;
    const int lane  = tid & 31;
    const int g     = lane >> 2;
    const int t2    = (lane & 3) * 2;
    const int quad  = lane >> 3;
    const int lrow  = lane & 7;
    const int row0  = qbase + 16 * w + g;

    u32 qh[12][4], ql[12][4];
    {
        const float* q0 = q + ((size_t)row0 * HH + h) * DQK;
        const float* q8 = q0 + (size_t)8 * HH * DQK;
        #pragma unroll
        for (int ks = 0; ks < 12; ks++) {
            int k0 = 16 * ks + t2;
            float2 v0 = *(const float2*)(q0 + k0);
            float2 v1 = *(const float2*)(q8 + k0);
            float2 v2 = *(const float2*)(q0 + k0 + 8);
            float2 v3 = *(const float2*)(q8 + k0 + 8);
            bsplit2(v0.x, v0.y, qh[ks][0], ql[ks][0]);
            bsplit2(v1.x, v1.y, qh[ks][1], ql[ks][1]);
            bsplit2(v2.x, v2.y, qh[ks][2], ql[ks][2]);
            bsplit2(v3.x, v3.y, qh[ks][3], ql[ks][3]);
        }
    }

    float oa[16][4];
    #pragma unroll
    for (int i = 0; i < 16; i++)
        #pragma unroll
        for (int j = 0; j < 4; j++) oa[i][j] = 0.0f;
    float m0 = -3.0e38f, m1 = -3.0e38f, l0 = 0.0f, l1 = 0.0f;

    const __nv_bfloat16* KhP = g_Khi  + (size_t)h * TT * DQK;
    const __nv_bfloat16* KlP = g_Klo  + (size_t)h * TT * DQK;
    const __nv_bfloat16* VhP = g_Vthi + (size_t)h * VD * TT;
    const __nv_bfloat16* VlP = g_Vtlo + (size_t)h * VD * TT;

    const int nt = 2 * qt + 2;

    stage_tile(tid, sb, 0, 0, KhP, KlP, VhP, VlP);
    CP_COMMIT();

    for (int tile = 0; tile < nt; tile++) {
        const u32 B = (tile & 1) ? (u32)BUFSZ : 0u;
        if (tile + 1 < nt) {
            stage_tile(tid, sb, (tile & 1) ? 0u : (u32)BUFSZ, 64 * (tile + 1),
                       KhP, KlP, VhP, VlP);
            CP_COMMIT();
            CP_WAIT1();
        } else {
            CP_WAIT0();
        }
        __syncthreads();

        float sa[8][4];
        #pragma unroll
        for (int i = 0; i < 8; i++)
            #pragma unroll
            for (int j = 0; j < 4; j++) sa[i][j] = 0.0f;

        const u32 kh_b = sb + B + KH_OFF;
        const u32 kl_b = sb + B + KL_OFF;
        #pragma unroll
        for (int na = 0; na < 8; na++) {
            const int rw = na * 8 + lrow;
            const u32 rbase2 = (u32)(rw * 384);
            #pragma unroll
            for (int ks2 = 0; ks2 < 6; ks2++) {
                const u32 coff = (u32)((((4 * ks2 + quad) ^ (rw & 7))) << 4);
                u32 r0, r1, r2, r3;
                LDSM4(r0, r1, r2, r3, kh_b + rbase2 + coff);
                MMA16816(sa[na], qh[2 * ks2],     r0, r1);
                MMA16816(sa[na], qh[2 * ks2 + 1], r2, r3);
                MMA16816(sa[na], ql[2 * ks2],     r0, r1);
                MMA16816(sa[na], ql[2 * ks2 + 1], r2, r3);
                u32 s0, s1, s2, s3;
                LDSM4(s0, s1, s2, s3, kl_b + rbase2 + coff);
                MMA16816(sa[na], qh[2 * ks2],     s0, s1);
                MMA16816(sa[na], qh[2 * ks2 + 1], s2, s3);
            }
        }

        const int kb = 64 * tile;
        const bool diag = (tile >= 2 * qt);
        float mx0 = -3.0e38f, mx1 = -3.0e38f;
        #pragma unroll
        for (int na = 0; na < 8; na++) {
            const int c = kb + 8 * na + t2;
            sa[na][0] *= SCALE_F; sa[na][1] *= SCALE_F;
            sa[na][2] *= SCALE_F; sa[na][3] *= SCALE_F;
            if (diag) {
                if (c     > row0)     sa[na][0] = -1.0e30f;
                if (c + 1 > row0)     sa[na][1] = -1.0e30f;
                if (c     > row0 + 8) sa[na][2] = -1.0e30f;
                if (c + 1 > row0 + 8) sa[na][3] = -1.0e30f;
            }
            mx0 = fmaxf(mx0, fmaxf(sa[na][0], sa[na][1]));
            mx1 = fmaxf(mx1, fmaxf(sa[na][2], sa[na][3]));
        }
        mx0 = fmaxf(mx0, __shfl_xor_sync(0xffffffffu, mx0, 1));
        mx0 = fmaxf(mx0, __shfl_xor_sync(0xffffffffu, mx0, 2));
        mx1 = fmaxf(mx1, __shfl_xor_sync(0xffffffffu, mx1, 1));
        mx1 = fmaxf(mx1, __shfl_xor_sync(0xffffffffu, mx1, 2));
        const float mn0 = fmaxf(m0, mx0), mn1 = fmaxf(m1, mx1);
        const float sc0 = __expf(m0 - mn0), sc1 = __expf(m1 - mn1);
        m0 = mn0; m1 = mn1;

        float sum0 = 0.0f, sum1 = 0.0f;
        #pragma unroll
        for (int na = 0; na < 8; na++) {
            sa[na][0] = __expf(sa[na][0] - mn0);
            sa[na][1] = __expf(sa[na][1] - mn0);
            sa[na][2] = __expf(sa[na][2] - mn1);
            sa[na][3] = __expf(sa[na][3] - mn1);
            sum0 += sa[na][0] + sa[na][1];
            sum1 += sa[na][2] + sa[na][3];
        }
        sum0 += __shfl_xor_sync(0xffffffffu, sum0, 1);
        sum0 += __shfl_xor_sync(0xffffffffu, sum0, 2);
        sum1 += __shfl_xor_sync(0xffffffffu, sum1, 1);
        sum1 += __shfl_xor_sync(0xffffffffu, sum1, 2);
        l0 = l0 * sc0 + sum0;
        l1 = l1 * sc1 + sum1;

        u32 ph[4][4], pl[4][4];
        #pragma unroll
        for (int ks = 0; ks < 4; ks++) {
            bsplit2(sa[2 * ks][0],     sa[2 * ks][1],     ph[ks][0], pl[ks][0]);
            bsplit2(sa[2 * ks][2],     sa[2 * ks][3],     ph[ks][1], pl[ks][1]);
            bsplit2(sa[2 * ks + 1][0], sa[2 * ks + 1][1], ph[ks][2], pl[ks][2]);
            bsplit2(sa[2 * ks + 1][2], sa[2 * ks + 1][3], ph[ks][3], pl[ks][3]);
        }

        #pragma unroll
        for (int na = 0; na < 16; na++) {
            oa[na][0] *= sc0; oa[na][1] *= sc0;
            oa[na][2] *= sc1; oa[na][3] *= sc1;
        }
        const u32 vh_b = sb + B + VH_OFF;
        const u32 vl_b = sb + B + VL_OFF;
        #pragma unroll
        for (int na = 0; na < 16; na++) {
            const int rw = na * 8 + lrow;
            const u32 rbase2 = (u32)(rw * 128);
            #pragma unroll
            for (int ks2 = 0; ks2 < 2; ks2++) {
                const u32 coff = (u32)((((4 * ks2 + quad) ^ (rw & 7))) << 4);
                u32 r0, r1, r2, r3;
                LDSM4(r0, r1, r2, r3, vh_b + rbase2 + coff);
                MMA16816(oa[na], ph[2 * ks2],     r0, r1);
                MMA16816(oa[na], ph[2 * ks2 + 1], r2, r3);
                MMA16816(oa[na], pl[2 * ks2],     r0, r1);
                MMA16816(oa[na], pl[2 * ks2 + 1], r2, r3);
                u32 s0, s1, s2, s3;
                LDSM4(s0, s1, s2, s3, vl_b + rbase2 + coff);
                MMA16816(oa[na], ph[2 * ks2],     s0, s1);
                MMA16816(oa[na], ph[2 * ks2 + 1], s2, s3);
            }
        }
        __syncthreads();
    }

    const float i0 = 1.0f / l0, i1 = 1.0f / l1;
    float* d0 = out + (size_t)row0 * (HH * VD) + h * VD;
    float* d8 = d0 + (size_t)8 * HH * VD;
    #pragma unroll
    for (int na = 0; na < 16; na++) {
        *(float2*)(d0 + 8 * na + t2) = make_float2(oa[na][0] * i0, oa[na][1] * i0);
        *(float2*)(d8 + 8 * na + t2) = make_float2(oa[na][2] * i1, oa[na][3] * i1);
    }
}

// ---------------------------------------------------------------------------
// Launch
// ---------------------------------------------------------------------------
extern "C" void kernel_launch(void* const* d_in, const int* in_sizes, int n_in,
                              void* d_out, int out_size)
{
    const float* query = (const float*)d_in[0];   // (T, H, 192)
    const float* kc    = (const float*)d_in[1];   // (T, 512)
    const float* kpe   = (const float*)d_in[2];   // (T, 64)
    const float* wkv   = (const float*)d_in[3];   // (512, 4096)
    const float* wuv   = (const float*)d_in[4];   // (16, 512, 128)
    float* out         = (float*)d_out;           // (T, 2048)

    conv_kc  <<<(TT * LORA / 2) / 256, 256>>>(kc);
    conv_w   <<<(4096 * 128) / 256,   256>>>(wkv, wuv);
    conv_rope<<<(HH * TT * 32) / 256, 256>>>(kpe);

    cudaFuncSetAttribute(proj_mma, cudaFuncAttributeMaxDynamicSharedMemorySize,
                         PROJ_SMEM);
    {
        dim3 grid(TT / 128, 32);
        proj_mma<<<grid, 256, PROJ_SMEM>>>();
    }

    cudaFuncSetAttribute(attn_kernel, cudaFuncAttributeMaxDynamicSharedMemorySize,
                         ATTN_SMEM);
    {
        dim3 grid(TT / 128, HH);
        attn_kernel<<<grid, 256, ATTN_SMEM>>>(query, out);
    }
}

// round 15
// speedup vs baseline: 3.6188x; 1.1370x over previous
#include <cuda_runtime.h>
#include <cuda_bf16.h>
#include <math.h>
#include <stdint.h>

#define TT   2048
#define HH   16
#define DQK  192
#define NOPE 128
#define ROPE 64
#define LORA 512
#define VD   128
#define SCALE_F (0.07216878364870322f)  // 1/sqrt(192)

typedef unsigned int u32;
typedef unsigned long long u64;

// ---------------------------------------------------------------------------
// Device scratch
// ---------------------------------------------------------------------------
__device__ __align__(16) __nv_bfloat16 g_Khi[HH * TT * DQK];   // [h][t][192]
__device__ __align__(16) __nv_bfloat16 g_Klo[HH * TT * DQK];
__device__ __align__(16) __nv_bfloat16 g_Vthi[HH * VD * TT];   // [h][n][t]
__device__ __align__(16) __nv_bfloat16 g_Vtlo[HH * VD * TT];
__device__ __align__(16) __nv_bfloat16 g_KChi[TT * LORA];      // A operand [t][l]
__device__ __align__(16) __nv_bfloat16 g_KClo[TT * LORA];
__device__ __align__(16) __nv_bfloat16 g_Wthi[4096 * LORA];    // B operand [n][l]
__device__ __align__(16) __nv_bfloat16 g_Wtlo[4096 * LORA];

// ---------------------------------------------------------------------------
// Helpers (arch-agnostic PTX only: mma.sync / ldmatrix / cp.async)
// ---------------------------------------------------------------------------
__device__ __forceinline__ u32 smem_u32(const void* p) {
    u32 a;
    asm("{ .reg .u64 t; cvta.to.shared.u64 t, %1; cvt.u32.u64 %0, t; }" : "=r"(a) : "l"(p));
    return a;
}

#define LDSM4(r0, r1, r2, r3, addr) \
    asm volatile("ldmatrix.sync.aligned.m8n8.x4.shared.b16 {%0,%1,%2,%3}, [%4];" \
        : "=r"(r0), "=r"(r1), "=r"(r2), "=r"(r3) : "r"(addr))

#define MMA16816(c, a, b0, b1) \
    asm volatile("mma.sync.aligned.m16n8k16.row.col.f32.bf16.bf16.f32 " \
        "{%0,%1,%2,%3}, {%4,%5,%6,%7}, {%8,%9}, {%0,%1,%2,%3};" \
        : "+f"((c)[0]), "+f"((c)[1]), "+f"((c)[2]), "+f"((c)[3]) \
        : "r"((a)[0]), "r"((a)[1]), "r"((a)[2]), "r"((a)[3]), "r"(b0), "r"(b1))

#define CP_ASYNC16(dst_u32, src_ptr) \
    asm volatile("cp.async.cg.shared.global [%0], [%1], 16;" :: "r"(dst_u32), "l"(src_ptr))
#define CP_COMMIT() asm volatile("cp.async.commit_group;" ::: "memory")
#define CP_WAIT1()  asm volatile("cp.async.wait_group 1;" ::: "memory")
#define CP_WAIT0()  asm volatile("cp.async.wait_group 0;" ::: "memory")

__device__ __forceinline__ void bsplit2(float a, float b, u32& hi, u32& lo) {
    __nv_bfloat16 ah = __float2bfloat16(a), bh = __float2bfloat16(b);
    float ar = a - __bfloat162float(ah);
    float br = b - __bfloat162float(bh);
    __nv_bfloat162 H; H.x = ah; H.y = bh;
    __nv_bfloat162 L; L.x = __float2bfloat16(ar); L.y = __float2bfloat16(br);
    hi = *(u32*)&H; lo = *(u32*)&L;
}
__device__ __forceinline__ void bsplit1(float x, __nv_bfloat16& hi, __nv_bfloat16& lo) {
    hi = __float2bfloat16(x);
    lo = __float2bfloat16(x - __bfloat162float(hi));
}

// ---------------------------------------------------------------------------
// Convert kernels (one-shot, memory-bound)
// ---------------------------------------------------------------------------
__global__ __launch_bounds__(256)
void conv_kc(const float* __restrict__ kc)
{
    int idx = blockIdx.x * 256 + threadIdx.x;
    if (idx >= TT * LORA / 2) return;
    float2 v = ((const float2*)kc)[idx];
    u32 hi, lo; bsplit2(v.x, v.y, hi, lo);
    ((u32*)g_KChi)[idx] = hi;
    ((u32*)g_KClo)[idx] = lo;
}

__global__ __launch_bounds__(256)
void conv_rope(const float* __restrict__ kpe)
{
    int idx = blockIdx.x * 256 + threadIdx.x;
    if (idx >= HH * TT * 32) return;
    int h = idx >> 16;
    int rem = idx & 65535;
    int t = rem >> 5, dp = rem & 31;
    float2 v = *(const float2*)(kpe + t * ROPE + 2 * dp);
    u32 hi, lo; bsplit2(v.x, v.y, hi, lo);
    size_t base = ((size_t)h * TT + t) * DQK + NOPE + 2 * dp;
    *(u32*)&g_Khi[base] = hi;
    *(u32*)&g_Klo[base] = lo;
}

__global__ __launch_bounds__(256)
void conv_w(const float* __restrict__ wkv, const float* __restrict__ wuv)
{
    int idx = blockIdx.x * 256 + threadIdx.x;
    if (idx >= 4096 * 128) return;
    int n = idx >> 7, lq = idx & 127;
    int l0 = lq * 4;
    float v[4];
    if (n < 2048) {
        int h = n >> 7, d = n & 127;
        const float* s = wkv + (size_t)l0 * 4096 + h * 256 + d;
        v[0] = s[0]; v[1] = s[4096]; v[2] = s[8192]; v[3] = s[12288];
    } else {
        int h = (n - 2048) >> 7, vd = n & 127;
        const float* s = wuv + ((size_t)h * LORA + l0) * VD + vd;
        v[0] = s[0]; v[1] = s[128]; v[2] = s[256]; v[3] = s[384];
    }
    __nv_bfloat16 h4[4], l4[4];
    #pragma unroll
    for (int i = 0; i < 4; i++) bsplit1(v[i], h4[i], l4[i]);
    size_t o = (size_t)n * LORA + l0;
    *(u64*)&g_Wthi[o] = *(u64*)h4;
    *(u64*)&g_Wtlo[o] = *(u64*)l4;
}

// ---------------------------------------------------------------------------
// Tensor-core projection GEMM (unchanged from R14 — tensor=48%, 87.6us)
// ---------------------------------------------------------------------------
#define PA_H 0
#define PA_L 16384
#define PB_H 32768
#define PB_L 49152
#define PBUF 65536
#define PROJ_SMEM (2 * PBUF)

__global__ __launch_bounds__(256, 1)
void proj_mma()
{
    extern __shared__ char smem[];
    const u32 sb = smem_u32(smem);

    const int bx = blockIdx.x;
    const int by = blockIdx.y;
    const int tbase = bx * 128, nbase = by * 128;
    const int tid  = threadIdx.x;
    const int w    = tid >> 5, lane = tid & 31;
    const int wm   = w & 1, wn = w >> 1;
    const int g    = lane >> 2, t2 = (lane & 3) * 2;
    const int quad = lane >> 3, lrow = lane & 7;

    float acc[4][4][4];
    #pragma unroll
    for (int i = 0; i < 4; i++)
        #pragma unroll
        for (int j = 0; j < 4; j++)
            #pragma unroll
            for (int k = 0; k < 4; k++) acc[i][j][k] = 0.0f;

    #define PROJ_STAGE(bo, kc_)                                                   \
        do {                                                                      \
            _Pragma("unroll")                                                     \
            for (int i = tid; i < 1024; i += 256) {                               \
                int row = i >> 3, c = i & 7;                                      \
                u32 off = (u32)(row * 128 + ((c ^ (row & 7)) << 4));              \
                size_t as = (size_t)(tbase + row) * LORA + (kc_) + c * 8;         \
                CP_ASYNC16(sb + (bo) + PA_H + off, (const char*)(g_KChi + as));   \
                CP_ASYNC16(sb + (bo) + PA_L + off, (const char*)(g_KClo + as));   \
                size_t bs = (size_t)(nbase + row) * LORA + (kc_) + c * 8;         \
                CP_ASYNC16(sb + (bo) + PB_H + off, (const char*)(g_Wthi + bs));   \
                CP_ASYNC16(sb + (bo) + PB_L + off, (const char*)(g_Wtlo + bs));   \
            }                                                                     \
        } while (0)

    PROJ_STAGE(0u, 0);
    CP_COMMIT();

    for (int kc = 0; kc < 8; kc++) {
        const u32 B = (kc & 1) ? (u32)PBUF : 0u;
        if (kc + 1 < 8) {
            PROJ_STAGE((kc & 1) ? 0u : (u32)PBUF, (kc + 1) * 64);
            CP_COMMIT();
            CP_WAIT1();
        } else {
            CP_WAIT0();
        }
        __syncthreads();

        #pragma unroll
        for (int ks2 = 0; ks2 < 2; ks2++) {
            u32 bh[4][4], bl[4][4];
            #pragma unroll
            for (int nb = 0; nb < 4; nb++) {
                int row = wn * 32 + nb * 8 + lrow;
                u32 off = (u32)(row * 128 + (((4 * ks2 + quad) ^ (row & 7)) << 4));
                LDSM4(bh[nb][0], bh[nb][1], bh[nb][2], bh[nb][3], sb + B + PB_H + off);
                LDSM4(bl[nb][0], bl[nb][1], bl[nb][2], bl[nb][3], sb + B + PB_L + off);
            }
            u32 ah[4][2][4], al[4][2][4];
            #pragma unroll
            for (int mb = 0; mb < 4; mb++) {
                int row = wm * 64 + mb * 16 + ((lane >> 3) & 1) * 8 + (lane & 7);
                #pragma unroll
                for (int kst = 0; kst < 2; kst++) {
                    int ch = 2 * (2 * ks2 + kst) + (lane >> 4);
                    u32 off = (u32)(row * 128 + ((ch ^ (row & 7)) << 4));
                    LDSM4(ah[mb][kst][0], ah[mb][kst][1], ah[mb][kst][2], ah[mb][kst][3],
                          sb + B + PA_H + off);
                    LDSM4(al[mb][kst][0], al[mb][kst][1], al[mb][kst][2], al[mb][kst][3],
                          sb + B + PA_L + off);
                }
            }
            #pragma unroll
            for (int kst = 0; kst < 2; kst++)
                #pragma unroll
                for (int nb = 0; nb < 4; nb++) {
                    u32 b0h = bh[nb][2 * kst], b1h = bh[nb][2 * kst + 1];
                    u32 b0l = bl[nb][2 * kst], b1l = bl[nb][2 * kst + 1];
                    #pragma unroll
                    for (int mb = 0; mb < 4; mb++) {
                        MMA16816(acc[mb][nb], ah[mb][kst], b0h, b1h);
                        MMA16816(acc[mb][nb], al[mb][kst], b0h, b1h);
                        MMA16816(acc[mb][nb], ah[mb][kst], b0l, b1l);
                    }
                }
        }
        __syncthreads();
    }

    if (by < 16) {
        const int h = by;
        #pragma unroll
        for (int mb = 0; mb < 4; mb++) {
            int t = tbase + wm * 64 + mb * 16 + g;
            #pragma unroll
            for (int nb = 0; nb < 4; nb++) {
                int d = wn * 32 + nb * 8 + t2;
                u32 hi, lo;
                bsplit2(acc[mb][nb][0], acc[mb][nb][1], hi, lo);
                size_t o = ((size_t)h * TT + t) * DQK + d;
                *(u32*)&g_Khi[o] = hi;  *(u32*)&g_Klo[o] = lo;
                bsplit2(acc[mb][nb][2], acc[mb][nb][3], hi, lo);
                o += (size_t)8 * DQK;
                *(u32*)&g_Khi[o] = hi;  *(u32*)&g_Klo[o] = lo;
            }
        }
    } else {
        const int h = by - 16;
        float* c_s = (float*)smem;
        #pragma unroll
        for (int mb = 0; mb < 4; mb++) {
            int r = wm * 64 + mb * 16 + g;
            #pragma unroll
            for (int nb = 0; nb < 4; nb++) {
                int c = wn * 32 + nb * 8 + t2;
                *(float2*)&c_s[r * 132 + c]       = make_float2(acc[mb][nb][0], acc[mb][nb][1]);
                *(float2*)&c_s[(r + 8) * 132 + c] = make_float2(acc[mb][nb][2], acc[mb][nb][3]);
            }
        }
        __syncthreads();
        #pragma unroll
        for (int i = tid; i < 4096; i += 256) {
            int n = i >> 5, tg = i & 31;
            int t0 = tg * 4;
            __nv_bfloat16 h4[4], l4[4];
            #pragma unroll
            for (int j = 0; j < 4; j++)
                bsplit1(c_s[(t0 + j) * 132 + n], h4[j], l4[j]);
            size_t o = ((size_t)h * VD + n) * TT + tbase + t0;
            *(u64*)&g_Vthi[o] = *(u64*)h4;
            *(u64*)&g_Vtlo[o] = *(u64*)l4;
        }
    }
}

// ---------------------------------------------------------------------------
// mma.sync flash attention — R15: MMA loops reordered so consecutive MMAs
// cycle over 4 independent accumulators (breaks the 36-deep RAW chains).
// ---------------------------------------------------------------------------
#define KH_OFF 0
#define KL_OFF 24576
#define VH_OFF 49152
#define VL_OFF 65536
#define BUFSZ  81920
#define ATTN_SMEM (2 * BUFSZ)

__device__ __forceinline__ void stage_tile(
    int tid, u32 sb, u32 bufoff, int kb,
    const __nv_bfloat16* Kh, const __nv_bfloat16* Kl,
    const __nv_bfloat16* Vh, const __nv_bfloat16* Vl)
{
    #pragma unroll
    for (int i = tid; i < 1536; i += 256) {
        int row = i / 24, c = i % 24;
        u32 dst = sb + bufoff + row * 384 + (u32)((c ^ (row & 7)) << 4);
        size_t src = (size_t)(kb + row) * DQK + c * 8;
        CP_ASYNC16(dst + KH_OFF, (const char*)(Kh + src));
        CP_ASYNC16(dst + KL_OFF, (const char*)(Kl + src));
    }
    #pragma unroll
    for (int i = tid; i < 1024; i += 256) {
        int row = i >> 3, c = i & 7;
        u32 dst = sb + bufoff + row * 128 + (u32)((c ^ (row & 7)) << 4);
        size_t src = (size_t)row * TT + kb + c * 8;
        CP_ASYNC16(dst + VH_OFF, (const char*)(Vh + src));
        CP_ASYNC16(dst + VL_OFF, (const char*)(Vl + src));
    }
}

__global__ __launch_bounds__(256, 1)
void attn_kernel(const float* __restrict__ q, float* __restrict__ out)
{
    extern __shared__ char smem[];
    const u32 sb = smem_u32(smem);

    const int h     = blockIdx.y;
    const int qt    = (int)gridDim.x - 1 - (int)blockIdx.x;
    const int qbase = qt * 128;
    const int tid   = threadIdx.x;
    const int w     = tid >> 5;
    const int lane  = tid & 31;
    const int g     = lane >> 2;
    const int t2    = (lane & 3) * 2;
    const int quad  = lane >> 3;
    const int lrow  = lane & 7;
    const int row0  = qbase + 16 * w + g;

    u32 qh[12][4], ql[12][4];
    {
        const float* q0 = q + ((size_t)row0 * HH + h) * DQK;
        const float* q8 = q0 + (size_t)8 * HH * DQK;
        #pragma unroll
        for (int ks = 0; ks < 12; ks++) {
            int k0 = 16 * ks + t2;
            float2 v0 = *(const float2*)(q0 + k0);
            float2 v1 = *(const float2*)(q8 + k0);
            float2 v2 = *(const float2*)(q0 + k0 + 8);
            float2 v3 = *(const float2*)(q8 + k0 + 8);
            bsplit2(v0.x, v0.y, qh[ks][0], ql[ks][0]);
            bsplit2(v1.x, v1.y, qh[ks][1], ql[ks][1]);
            bsplit2(v2.x, v2.y, qh[ks][2], ql[ks][2]);
            bsplit2(v3.x, v3.y, qh[ks][3], ql[ks][3]);
        }
    }

    float oa[16][4];
    #pragma unroll
    for (int i = 0; i < 16; i++)
        #pragma unroll
        for (int j = 0; j < 4; j++) oa[i][j] = 0.0f;
    float m0 = -3.0e38f, m1 = -3.0e38f, l0 = 0.0f, l1 = 0.0f;

    const __nv_bfloat16* KhP = g_Khi  + (size_t)h * TT * DQK;
    const __nv_bfloat16* KlP = g_Klo  + (size_t)h * TT * DQK;
    const __nv_bfloat16* VhP = g_Vthi + (size_t)h * VD * TT;
    const __nv_bfloat16* VlP = g_Vtlo + (size_t)h * VD * TT;

    const int nt = 2 * qt + 2;

    stage_tile(tid, sb, 0, 0, KhP, KlP, VhP, VlP);
    CP_COMMIT();

    for (int tile = 0; tile < nt; tile++) {
        const u32 B = (tile & 1) ? (u32)BUFSZ : 0u;
        if (tile + 1 < nt) {
            stage_tile(tid, sb, (tile & 1) ? 0u : (u32)BUFSZ, 64 * (tile + 1),
                       KhP, KlP, VhP, VlP);
            CP_COMMIT();
            CP_WAIT1();
        } else {
            CP_WAIT0();
        }
        __syncthreads();

        // --- QK: groups of 4 na -> 4 independent accumulator chains ---
        float sa[8][4];
        #pragma unroll
        for (int i = 0; i < 8; i++)
            #pragma unroll
            for (int j = 0; j < 4; j++) sa[i][j] = 0.0f;

        const u32 kh_b = sb + B + KH_OFF;
        const u32 kl_b = sb + B + KL_OFF;
        #pragma unroll
        for (int ng = 0; ng < 2; ng++) {
            #pragma unroll
            for (int ks2 = 0; ks2 < 6; ks2++) {
                u32 kh[4][4], kl[4][4];
                #pragma unroll
                for (int j = 0; j < 4; j++) {
                    const int rw = (ng * 4 + j) * 8 + lrow;
                    const u32 off = (u32)(rw * 384 + (((4 * ks2 + quad) ^ (rw & 7)) << 4));
                    LDSM4(kh[j][0], kh[j][1], kh[j][2], kh[j][3], kh_b + off);
                    LDSM4(kl[j][0], kl[j][1], kl[j][2], kl[j][3], kl_b + off);
                }
                #pragma unroll
                for (int j = 0; j < 4; j++) MMA16816(sa[ng*4+j], qh[2*ks2],   kh[j][0], kh[j][1]);
                #pragma unroll
                for (int j = 0; j < 4; j++) MMA16816(sa[ng*4+j], qh[2*ks2+1], kh[j][2], kh[j][3]);
                #pragma unroll
                for (int j = 0; j < 4; j++) MMA16816(sa[ng*4+j], ql[2*ks2],   kh[j][0], kh[j][1]);
                #pragma unroll
                for (int j = 0; j < 4; j++) MMA16816(sa[ng*4+j], ql[2*ks2+1], kh[j][2], kh[j][3]);
                #pragma unroll
                for (int j = 0; j < 4; j++) MMA16816(sa[ng*4+j], qh[2*ks2],   kl[j][0], kl[j][1]);
                #pragma unroll
                for (int j = 0; j < 4; j++) MMA16816(sa[ng*4+j], qh[2*ks2+1], kl[j][2], kl[j][3]);
            }
        }

        const int kb = 64 * tile;
        const bool diag = (tile >= 2 * qt);
        float mx0 = -3.0e38f, mx1 = -3.0e38f;
        #pragma unroll
        for (int na = 0; na < 8; na++) {
            const int c = kb + 8 * na + t2;
            sa[na][0] *= SCALE_F; sa[na][1] *= SCALE_F;
            sa[na][2] *= SCALE_F; sa[na][3] *= SCALE_F;
            if (diag) {
                if (c     > row0)     sa[na][0] = -1.0e30f;
                if (c + 1 > row0)     sa[na][1] = -1.0e30f;
                if (c     > row0 + 8) sa[na][2] = -1.0e30f;
                if (c + 1 > row0 + 8) sa[na][3] = -1.0e30f;
            }
            mx0 = fmaxf(mx0, fmaxf(sa[na][0], sa[na][1]));
            mx1 = fmaxf(mx1, fmaxf(sa[na][2], sa[na][3]));
        }
        mx0 = fmaxf(mx0, __shfl_xor_sync(0xffffffffu, mx0, 1));
        mx0 = fmaxf(mx0, __shfl_xor_sync(0xffffffffu, mx0, 2));
        mx1 = fmaxf(mx1, __shfl_xor_sync(0xffffffffu, mx1, 1));
        mx1 = fmaxf(mx1, __shfl_xor_sync(0xffffffffu, mx1, 2));
        const float mn0 = fmaxf(m0, mx0), mn1 = fmaxf(m1, mx1);
        const float sc0 = __expf(m0 - mn0), sc1 = __expf(m1 - mn1);
        m0 = mn0; m1 = mn1;

        float sum0 = 0.0f, sum1 = 0.0f;
        #pragma unroll
        for (int na = 0; na < 8; na++) {
            sa[na][0] = __expf(sa[na][0] - mn0);
            sa[na][1] = __expf(sa[na][1] - mn0);
            sa[na][2] = __expf(sa[na][2] - mn1);
            sa[na][3] = __expf(sa[na][3] - mn1);
            sum0 += sa[na][0] + sa[na][1];
            sum1 += sa[na][2] + sa[na][3];
        }
        sum0 += __shfl_xor_sync(0xffffffffu, sum0, 1);
        sum0 += __shfl_xor_sync(0xffffffffu, sum0, 2);
        sum1 += __shfl_xor_sync(0xffffffffu, sum1, 1);
        sum1 += __shfl_xor_sync(0xffffffffu, sum1, 2);
        l0 = l0 * sc0 + sum0;
        l1 = l1 * sc1 + sum1;

        u32 ph[4][4], pl[4][4];
        #pragma unroll
        for (int ks = 0; ks < 4; ks++) {
            bsplit2(sa[2 * ks][0],     sa[2 * ks][1],     ph[ks][0], pl[ks][0]);
            bsplit2(sa[2 * ks][2],     sa[2 * ks][3],     ph[ks][1], pl[ks][1]);
            bsplit2(sa[2 * ks + 1][0], sa[2 * ks + 1][1], ph[ks][2], pl[ks][2]);
            bsplit2(sa[2 * ks + 1][2], sa[2 * ks + 1][3], ph[ks][3], pl[ks][3]);
        }

        #pragma unroll
        for (int na = 0; na < 16; na++) {
            oa[na][0] *= sc0; oa[na][1] *= sc0;
            oa[na][2] *= sc1; oa[na][3] *= sc1;
        }

        // --- PV: groups of 4 na -> 4 independent accumulator chains ---
        const u32 vh_b = sb + B + VH_OFF;
        const u32 vl_b = sb + B + VL_OFF;
        #pragma unroll
        for (int ks2 = 0; ks2 < 2; ks2++) {
            #pragma unroll
            for (int ng = 0; ng < 4; ng++) {
                u32 vh[4][4], vl[4][4];
                #pragma unroll
                for (int j = 0; j < 4; j++) {
                    const int rw = (ng * 4 + j) * 8 + lrow;
                    const u32 off = (u32)(rw * 128 + (((4 * ks2 + quad) ^ (rw & 7)) << 4));
                    LDSM4(vh[j][0], vh[j][1], vh[j][2], vh[j][3], vh_b + off);
                    LDSM4(vl[j][0], vl[j][1], vl[j][2], vl[j][3], vl_b + off);
                }
                #pragma unroll
                for (int j = 0; j < 4; j++) MMA16816(oa[ng*4+j], ph[2*ks2],   vh[j][0], vh[j][1]);
                #pragma unroll
                for (int j = 0; j < 4; j++) MMA16816(oa[ng*4+j], ph[2*ks2+1], vh[j][2], vh[j][3]);
                #pragma unroll
                for (int j = 0; j < 4; j++) MMA16816(oa[ng*4+j], pl[2*ks2],   vh[j][0], vh[j][1]);
                #pragma unroll
                for (int j = 0; j < 4; j++) MMA16816(oa[ng*4+j], pl[2*ks2+1], vh[j][2], vh[j][3]);
                #pragma unroll
                for (int j = 0; j < 4; j++) MMA16816(oa[ng*4+j], ph[2*ks2],   vl[j][0], vl[j][1]);
                #pragma unroll
                for (int j = 0; j < 4; j++) MMA16816(oa[ng*4+j], ph[2*ks2+1], vl[j][2], vl[j][3]);
            }
        }
        __syncthreads();
    }

    const float i0 = 1.0f / l0, i1 = 1.0f / l1;
    float* d0 = out + (size_t)row0 * (HH * VD) + h * VD;
    float* d8 = d0 + (size_t)8 * HH * VD;
    #pragma unroll
    for (int na = 0; na < 16; na++) {
        *(float2*)(d0 + 8 * na + t2) = make_float2(oa[na][0] * i0, oa[na][1] * i0);
        *(float2*)(d8 + 8 * na + t2) = make_float2(oa[na][2] * i1, oa[na][3] * i1);
    }
}

// ---------------------------------------------------------------------------
// Launch
// ---------------------------------------------------------------------------
extern "C" void kernel_launch(void* const* d_in, const int* in_sizes, int n_in,
                              void* d_out, int out_size)
{
    const float* query = (const float*)d_in[0];   // (T, H, 192)
    const float* kc    = (const float*)d_in[1];   // (T, 512)
    const float* kpe   = (const float*)d_in[2];   // (T, 64)
    const float* wkv   = (const float*)d_in[3];   // (512, 4096)
    const float* wuv   = (const float*)d_in[4];   // (16, 512, 128)
    float* out         = (float*)d_out;           // (T, 2048)

    conv_kc  <<<(TT * LORA / 2) / 256, 256>>>(kc);
    conv_w   <<<(4096 * 128) / 256,   256>>>(wkv, wuv);
    conv_rope<<<(HH * TT * 32) / 256, 256>>>(kpe);

    cudaFuncSetAttribute(proj_mma, cudaFuncAttributeMaxDynamicSharedMemorySize,
                         PROJ_SMEM);
    {
        dim3 grid(TT / 128, 32);
        proj_mma<<<grid, 256, PROJ_SMEM>>>();
    }

    cudaFuncSetAttribute(attn_kernel, cudaFuncAttributeMaxDynamicSharedMemorySize,
                         ATTN_SMEM);
    {
        dim3 grid(TT / 128, HH);
        attn_kernel<<<grid, 256, ATTN_SMEM>>>(query, out);
    }
}